// round 15
// baseline (speedup 1.0000x reference)
#include <cuda_runtime.h>
#include <cstdint>

// Divergence of (average(M) * gradient(mu)) with periodic boundaries.
// Shapes: (B=16, C=1, H=1024, W=1024) fp32.
// out[p] = sum_ax [ v_ax(p) - v_ax(p - e_ax) ],  v_ax(p) = 0.5*(M[p+e]+M[p])*(mu[p+e]-mu[p])
//
// 8-row register-burst kernel. Each thread: one float4 column x 8 output
// rows; 10 rows x 2 arrays = 20 independent float4 loads, front-batched.
// Read amplification 10/8 = 1.25 (vs 1.5 for 4-row strips).
// Horizontal halos: ONE warp-cooperative scalar load per warp covers all 32
// (side, array, row) halo values; redistributed via shuffle at use time.
// No lane-specialized register arrays, no in-loop memory dependencies.

#define H_DIM 1024
#define W_DIM 1024
#define N_IMG 16
#define RSTRIP 8
#define NROWS (RSTRIP + 2)   // 10

__device__ __forceinline__ float4 row_result(
    const float4 m, const float4 u,
    float mL, float uL, float mR, float uR,
    const float4 mup, const float4 uup,
    const float4 mdn, const float4 udn)
{
    // W-direction forward fluxes (backward flux of elem e == forward of e-1)
    float vm = 0.5f * (m.x + mL)  * (u.x - uL);
    float v0 = 0.5f * (m.y + m.x) * (u.y - u.x);
    float v1 = 0.5f * (m.z + m.y) * (u.z - u.y);
    float v2 = 0.5f * (m.w + m.z) * (u.w - u.z);
    float v3 = 0.5f * (mR  + m.w) * (uR  - u.w);

    float4 r;
    r.x = (v0 - vm) + 0.5f * (mdn.x + m.x) * (udn.x - u.x) - 0.5f * (m.x + mup.x) * (u.x - uup.x);
    r.y = (v1 - v0) + 0.5f * (mdn.y + m.y) * (udn.y - u.y) - 0.5f * (m.y + mup.y) * (u.y - uup.y);
    r.z = (v2 - v1) + 0.5f * (mdn.z + m.z) * (udn.z - u.z) - 0.5f * (m.z + mup.z) * (u.z - uup.z);
    r.w = (v3 - v2) + 0.5f * (mdn.w + m.w) * (udn.w - u.w) - 0.5f * (m.w + mup.w) * (u.w - uup.w);
    return r;
}

__global__ __launch_bounds__(256, 3) void div_grad_kernel(
    const float* __restrict__ M,
    const float* __restrict__ mu,
    float* __restrict__ out)
{
    const int t     = threadIdx.x;         // 0..255 : float4 column
    const int lane  = t & 31;
    const int strip = blockIdx.x & 127;    // 128 strips of 8 rows per image
    const int img   = blockIdx.x >> 7;

    const int h0 = strip << 3;             // 0..1016
    const size_t base = (size_t)img << 20;
    const float* Mi = M  + base;
    const float* Ui = mu + base;
    const int wb = t << 2;

    // ---- Warp-cooperative halo load (1 scalar per lane, in the burst) ----
    // lane l: row = l&7 (h0..h0+7, never wraps), array = (l>>3)&1 (0=M,1=mu),
    //         side = l>>4 (0=left, 1=right)
    const int warp_first = (t & ~31) << 2;             // first float of warp
    const int colL = (warp_first - 1) & (W_DIM - 1);
    const int colR = (warp_first + 128) & (W_DIM - 1);
    const int hl_row  = h0 + (lane & 7);
    const int hl_col  = (lane >> 4) ? colR : colL;
    const float* hl_p = ((lane >> 3) & 1) ? Ui : Mi;
    const float halo = __ldg(hl_p + ((size_t)hl_row << 10) + hl_col);

    // ---- Main burst: 20 independent float4 loads ----
    float4 m[NROWS], u[NROWS];
    if (h0 != 0 && h0 != (H_DIM - RSTRIP)) {
        // Fast path (126/128): rows h0-1 .. h0+8 contiguous.
        const float* Mb = Mi + (((size_t)(h0 - 1)) << 10) + wb;
        const float* Ub = Ui + (((size_t)(h0 - 1)) << 10) + wb;
        #pragma unroll
        for (int i = 0; i < NROWS; ++i)
            m[i] = *reinterpret_cast<const float4*>(Mb + (i << 10));
        #pragma unroll
        for (int i = 0; i < NROWS; ++i)
            u[i] = *reinterpret_cast<const float4*>(Ub + (i << 10));
    } else {
        // Slow path (2 strips): wrap-aware rows.
        #pragma unroll
        for (int i = 0; i < NROWS; ++i) {
            const int hr = (h0 - 1 + i) & (H_DIM - 1);
            m[i] = *reinterpret_cast<const float4*>(Mi + ((size_t)hr << 10) + wb);
            u[i] = *reinterpret_cast<const float4*>(Ui + ((size_t)hr << 10) + wb);
        }
    }

    const unsigned FULL = 0xffffffffu;
    float* Oi = out + base;

    #pragma unroll
    for (int r = 0; r < RSTRIP; ++r) {
        const int c = r + 1;

        // Neighbor halos via shuffle; warp-edge lanes take the cooperative
        // halo values broadcast from the owning lanes.
        float lM = __shfl_up_sync(FULL, m[c].w, 1);
        float lU = __shfl_up_sync(FULL, u[c].w, 1);
        float rM = __shfl_down_sync(FULL, m[c].x, 1);
        float rU = __shfl_down_sync(FULL, u[c].x, 1);

        const float hlM = __shfl_sync(FULL, halo, r);        // left,  M
        const float hlU = __shfl_sync(FULL, halo, 8 + r);    // left,  mu
        const float hrM = __shfl_sync(FULL, halo, 16 + r);   // right, M
        const float hrU = __shfl_sync(FULL, halo, 24 + r);   // right, mu

        if (lane == 0)       { lM = hlM; lU = hlU; }
        else if (lane == 31) { rM = hrM; rU = hrU; }

        float4 res = row_result(m[c], u[c], lM, lU, rM, rU,
                                m[c - 1], u[c - 1], m[c + 1], u[c + 1]);
        *reinterpret_cast<float4*>(Oi + ((size_t)(h0 + r) << 10) + wb) = res;
    }
}

extern "C" void kernel_launch(void* const* d_in, const int* in_sizes, int n_in,
                              void* d_out, int out_size)
{
    const float* M  = (const float*)d_in[0];
    const float* mu = (const float*)d_in[1];
    float* out = (float*)d_out;

    const int grid = N_IMG * (H_DIM / RSTRIP);  // 2048 blocks
    div_grad_kernel<<<grid, 256>>>(M, mu, out);
}

// round 16
// speedup vs baseline: 1.4702x; 1.4702x over previous
#include <cuda_runtime.h>
#include <cstdint>

// Divergence of (average(M) * gradient(mu)) with periodic boundaries.
// Shapes: (B=16, C=1, H=1024, W=1024) fp32.
// out[p] = sum_ax [ v_ax(p) - v_ax(p - e_ax) ],  v_ax(p) = 0.5*(M[p+e]+M[p])*(mu[p+e]-mu[p])
//
// 6-row register-burst kernel. Each thread: one float4 column x 6 output
// rows; 8 rows x 2 arrays = 16 independent float4 loads, front-batched
// (64 data regs -> fits the 85-reg/3-CTA budget without spilling).
// Read amplification 8/6 = 1.33.
// Horizontal halos: one warp-cooperative scalar load covers all 24
// (side, array, row) halo values; redistributed via shuffle at use time.
// Streaming stores keep the output from polluting L2.

#define H_DIM 1024
#define W_DIM 1024
#define N_IMG 16
#define RSTRIP 6
#define NROWS (RSTRIP + 2)   // 8

__device__ __forceinline__ float4 row_result(
    const float4 m, const float4 u,
    float mL, float uL, float mR, float uR,
    const float4 mup, const float4 uup,
    const float4 mdn, const float4 udn)
{
    // W-direction forward fluxes (backward flux of elem e == forward of e-1)
    float vm = 0.5f * (m.x + mL)  * (u.x - uL);
    float v0 = 0.5f * (m.y + m.x) * (u.y - u.x);
    float v1 = 0.5f * (m.z + m.y) * (u.z - u.y);
    float v2 = 0.5f * (m.w + m.z) * (u.w - u.z);
    float v3 = 0.5f * (mR  + m.w) * (uR  - u.w);

    float4 r;
    r.x = (v0 - vm) + 0.5f * (mdn.x + m.x) * (udn.x - u.x) - 0.5f * (m.x + mup.x) * (u.x - uup.x);
    r.y = (v1 - v0) + 0.5f * (mdn.y + m.y) * (udn.y - u.y) - 0.5f * (m.y + mup.y) * (u.y - uup.y);
    r.z = (v2 - v1) + 0.5f * (mdn.z + m.z) * (udn.z - u.z) - 0.5f * (m.z + mup.z) * (u.z - uup.z);
    r.w = (v3 - v2) + 0.5f * (mdn.w + m.w) * (udn.w - u.w) - 0.5f * (m.w + mup.w) * (u.w - uup.w);
    return r;
}

__global__ __launch_bounds__(256, 3) void div_grad_kernel(
    const float* __restrict__ M,
    const float* __restrict__ mu,
    float* __restrict__ out)
{
    const int t     = threadIdx.x;         // 0..255 : float4 column
    const int lane  = t & 31;
    // 1024 rows: strips of 6 rows; last strip handled by grid sizing (1024 = 170*6 + 4)
    // We use 512 strips of 2 images... simpler: H/RSTRIP is not integral for 6.
    // Instead: 1024 = 6*170 + 4 -> avoid; use strip count 171 with clamp? No.
    // Solution: grid covers ceil(1024/6)=171 strips; last strip recomputes rows 1018..1023
    const int strip = blockIdx.x % 171;
    const int img   = blockIdx.x / 171;

    int h0 = strip * RSTRIP;
    if (h0 > H_DIM - RSTRIP) h0 = H_DIM - RSTRIP;   // overlap: rows recomputed, same values

    const size_t base = (size_t)img << 20;
    const float* Mi = M  + base;
    const float* Ui = mu + base;
    const int wb = t << 2;

    // ---- Warp-cooperative halo load (1 scalar per lane, in the burst) ----
    // lane l (l < 24): row = l%6 (h0..h0+5), array = (l/6)&1 (0=M,1=mu),
    //                  side = l/12 (0=left, 1=right)
    const int warp_first = (t & ~31) << 2;             // first float of warp
    const int colL = (warp_first - 1) & (W_DIM - 1);
    const int colR = (warp_first + 128) & (W_DIM - 1);
    const int hrow6   = lane % 6;                      // 0..5 (lanes >=24 harmless dup)
    const int hl_sel  = (lane / 6) & 1;
    const int hl_side = (lane >= 12 && lane < 24) ? 1 : (lane >= 24 ? 1 : 0);
    // simpler exact mapping for lanes 0..23; lanes 24..31 load a duplicate
    const int     l24   = (lane < 24) ? lane : (lane - 24);
    const int     hrow  = h0 + (l24 % 6);
    const int     harr  = (l24 / 6) & 1;               // 0:M-left,1:mu-left,2:M-right,3:mu-right -> arr=(l24/6)%2? no:
    // groups of 6: g = l24/6 in 0..3 ; g0: M-left, g1: mu-left, g2: M-right, g3: mu-right
    const int     g     = l24 / 6;
    const int     hcol  = (g >= 2) ? colR : colL;
    const float*  hp    = (g & 1) ? Ui : Mi;
    const float halo = __ldg(hp + ((size_t)hrow << 10) + hcol);
    (void)hrow6; (void)hl_sel; (void)hl_side; (void)harr;

    // ---- Main burst: 16 independent float4 loads ----
    float4 m[NROWS], u[NROWS];
    if (h0 != 0 && h0 != (H_DIM - RSTRIP)) {
        // Fast path: rows h0-1 .. h0+6 contiguous.
        const float* Mb = Mi + (((size_t)(h0 - 1)) << 10) + wb;
        const float* Ub = Ui + (((size_t)(h0 - 1)) << 10) + wb;
        #pragma unroll
        for (int i = 0; i < NROWS; ++i)
            m[i] = *reinterpret_cast<const float4*>(Mb + (i << 10));
        #pragma unroll
        for (int i = 0; i < NROWS; ++i)
            u[i] = *reinterpret_cast<const float4*>(Ub + (i << 10));
    } else {
        // Slow path: wrap-aware rows.
        #pragma unroll
        for (int i = 0; i < NROWS; ++i) {
            const int hr = (h0 - 1 + i) & (H_DIM - 1);
            m[i] = *reinterpret_cast<const float4*>(Mi + ((size_t)hr << 10) + wb);
            u[i] = *reinterpret_cast<const float4*>(Ui + ((size_t)hr << 10) + wb);
        }
    }

    const unsigned FULL = 0xffffffffu;
    float* Oi = out + base;

    #pragma unroll
    for (int r = 0; r < RSTRIP; ++r) {
        const int c = r + 1;

        // Neighbor halos via shuffle; warp-edge lanes take cooperative values.
        float lM = __shfl_up_sync(FULL, m[c].w, 1);
        float lU = __shfl_up_sync(FULL, u[c].w, 1);
        float rM = __shfl_down_sync(FULL, m[c].x, 1);
        float rU = __shfl_down_sync(FULL, u[c].x, 1);

        const float hlM = __shfl_sync(FULL, halo, r);        // g0: M-left
        const float hlU = __shfl_sync(FULL, halo, 6 + r);    // g1: mu-left
        const float hrM = __shfl_sync(FULL, halo, 12 + r);   // g2: M-right
        const float hrU = __shfl_sync(FULL, halo, 18 + r);   // g3: mu-right

        if (lane == 0)       { lM = hlM; lU = hlU; }
        else if (lane == 31) { rM = hrM; rU = hrU; }

        float4 res = row_result(m[c], u[c], lM, lU, rM, rU,
                                m[c - 1], u[c - 1], m[c + 1], u[c + 1]);
        __stcs(reinterpret_cast<float4*>(Oi + ((size_t)(h0 + r) << 10) + wb), res);
    }
}

extern "C" void kernel_launch(void* const* d_in, const int* in_sizes, int n_in,
                              void* d_out, int out_size)
{
    const float* M  = (const float*)d_in[0];
    const float* mu = (const float*)d_in[1];
    float* out = (float*)d_out;

    const int grid = N_IMG * 171;   // ceil(1024/6) strips per image (last overlaps)
    div_grad_kernel<<<grid, 256>>>(M, mu, out);
}

// round 17
// speedup vs baseline: 1.4715x; 1.0009x over previous
#include <cuda_runtime.h>
#include <cstdint>

// Divergence of (average(M) * gradient(mu)) with periodic boundaries.
// Shapes: (B=16, C=1, H=1024, W=1024) fp32.
// out[p] = sum_ax [ v_ax(p) - v_ax(p - e_ax) ],  v_ax(p) = 0.5*(M[p+e]+M[p])*(mu[p+e]-mu[p])
//
// 6-row register-burst kernel. Each thread: one float4 column x 6 output
// rows; 8 rows x 2 arrays = 16 independent float4 loads, front-batched
// (64 data regs -> fits the 85-reg/3-CTA budget without spilling).
// Read amplification 8/6 = 1.33.
// Horizontal halos: one warp-cooperative scalar load covers all 24
// (side, array, row) halo values; redistributed via shuffle at use time.
// Streaming stores keep the output from polluting L2.

#define H_DIM 1024
#define W_DIM 1024
#define N_IMG 16
#define RSTRIP 6
#define NROWS (RSTRIP + 2)   // 8

__device__ __forceinline__ float4 row_result(
    const float4 m, const float4 u,
    float mL, float uL, float mR, float uR,
    const float4 mup, const float4 uup,
    const float4 mdn, const float4 udn)
{
    // W-direction forward fluxes (backward flux of elem e == forward of e-1)
    float vm = 0.5f * (m.x + mL)  * (u.x - uL);
    float v0 = 0.5f * (m.y + m.x) * (u.y - u.x);
    float v1 = 0.5f * (m.z + m.y) * (u.z - u.y);
    float v2 = 0.5f * (m.w + m.z) * (u.w - u.z);
    float v3 = 0.5f * (mR  + m.w) * (uR  - u.w);

    float4 r;
    r.x = (v0 - vm) + 0.5f * (mdn.x + m.x) * (udn.x - u.x) - 0.5f * (m.x + mup.x) * (u.x - uup.x);
    r.y = (v1 - v0) + 0.5f * (mdn.y + m.y) * (udn.y - u.y) - 0.5f * (m.y + mup.y) * (u.y - uup.y);
    r.z = (v2 - v1) + 0.5f * (mdn.z + m.z) * (udn.z - u.z) - 0.5f * (m.z + mup.z) * (u.z - uup.z);
    r.w = (v3 - v2) + 0.5f * (mdn.w + m.w) * (udn.w - u.w) - 0.5f * (m.w + mup.w) * (u.w - uup.w);
    return r;
}

__global__ __launch_bounds__(256, 3) void div_grad_kernel(
    const float* __restrict__ M,
    const float* __restrict__ mu,
    float* __restrict__ out)
{
    const int t     = threadIdx.x;         // 0..255 : float4 column
    const int lane  = t & 31;
    // 1024 rows: strips of 6 rows; last strip handled by grid sizing (1024 = 170*6 + 4)
    // We use 512 strips of 2 images... simpler: H/RSTRIP is not integral for 6.
    // Instead: 1024 = 6*170 + 4 -> avoid; use strip count 171 with clamp? No.
    // Solution: grid covers ceil(1024/6)=171 strips; last strip recomputes rows 1018..1023
    const int strip = blockIdx.x % 171;
    const int img   = blockIdx.x / 171;

    int h0 = strip * RSTRIP;
    if (h0 > H_DIM - RSTRIP) h0 = H_DIM - RSTRIP;   // overlap: rows recomputed, same values

    const size_t base = (size_t)img << 20;
    const float* Mi = M  + base;
    const float* Ui = mu + base;
    const int wb = t << 2;

    // ---- Warp-cooperative halo load (1 scalar per lane, in the burst) ----
    // lane l (l < 24): row = l%6 (h0..h0+5), array = (l/6)&1 (0=M,1=mu),
    //                  side = l/12 (0=left, 1=right)
    const int warp_first = (t & ~31) << 2;             // first float of warp
    const int colL = (warp_first - 1) & (W_DIM - 1);
    const int colR = (warp_first + 128) & (W_DIM - 1);
    const int hrow6   = lane % 6;                      // 0..5 (lanes >=24 harmless dup)
    const int hl_sel  = (lane / 6) & 1;
    const int hl_side = (lane >= 12 && lane < 24) ? 1 : (lane >= 24 ? 1 : 0);
    // simpler exact mapping for lanes 0..23; lanes 24..31 load a duplicate
    const int     l24   = (lane < 24) ? lane : (lane - 24);
    const int     hrow  = h0 + (l24 % 6);
    const int     harr  = (l24 / 6) & 1;               // 0:M-left,1:mu-left,2:M-right,3:mu-right -> arr=(l24/6)%2? no:
    // groups of 6: g = l24/6 in 0..3 ; g0: M-left, g1: mu-left, g2: M-right, g3: mu-right
    const int     g     = l24 / 6;
    const int     hcol  = (g >= 2) ? colR : colL;
    const float*  hp    = (g & 1) ? Ui : Mi;
    const float halo = __ldg(hp + ((size_t)hrow << 10) + hcol);
    (void)hrow6; (void)hl_sel; (void)hl_side; (void)harr;

    // ---- Main burst: 16 independent float4 loads ----
    float4 m[NROWS], u[NROWS];
    if (h0 != 0 && h0 != (H_DIM - RSTRIP)) {
        // Fast path: rows h0-1 .. h0+6 contiguous.
        const float* Mb = Mi + (((size_t)(h0 - 1)) << 10) + wb;
        const float* Ub = Ui + (((size_t)(h0 - 1)) << 10) + wb;
        #pragma unroll
        for (int i = 0; i < NROWS; ++i)
            m[i] = *reinterpret_cast<const float4*>(Mb + (i << 10));
        #pragma unroll
        for (int i = 0; i < NROWS; ++i)
            u[i] = *reinterpret_cast<const float4*>(Ub + (i << 10));
    } else {
        // Slow path: wrap-aware rows.
        #pragma unroll
        for (int i = 0; i < NROWS; ++i) {
            const int hr = (h0 - 1 + i) & (H_DIM - 1);
            m[i] = *reinterpret_cast<const float4*>(Mi + ((size_t)hr << 10) + wb);
            u[i] = *reinterpret_cast<const float4*>(Ui + ((size_t)hr << 10) + wb);
        }
    }

    const unsigned FULL = 0xffffffffu;
    float* Oi = out + base;

    #pragma unroll
    for (int r = 0; r < RSTRIP; ++r) {
        const int c = r + 1;

        // Neighbor halos via shuffle; warp-edge lanes take cooperative values.
        float lM = __shfl_up_sync(FULL, m[c].w, 1);
        float lU = __shfl_up_sync(FULL, u[c].w, 1);
        float rM = __shfl_down_sync(FULL, m[c].x, 1);
        float rU = __shfl_down_sync(FULL, u[c].x, 1);

        const float hlM = __shfl_sync(FULL, halo, r);        // g0: M-left
        const float hlU = __shfl_sync(FULL, halo, 6 + r);    // g1: mu-left
        const float hrM = __shfl_sync(FULL, halo, 12 + r);   // g2: M-right
        const float hrU = __shfl_sync(FULL, halo, 18 + r);   // g3: mu-right

        if (lane == 0)       { lM = hlM; lU = hlU; }
        else if (lane == 31) { rM = hrM; rU = hrU; }

        float4 res = row_result(m[c], u[c], lM, lU, rM, rU,
                                m[c - 1], u[c - 1], m[c + 1], u[c + 1]);
        __stcs(reinterpret_cast<float4*>(Oi + ((size_t)(h0 + r) << 10) + wb), res);
    }
}

extern "C" void kernel_launch(void* const* d_in, const int* in_sizes, int n_in,
                              void* d_out, int out_size)
{
    const float* M  = (const float*)d_in[0];
    const float* mu = (const float*)d_in[1];
    float* out = (float*)d_out;

    const int grid = N_IMG * 171;   // ceil(1024/6) strips per image (last overlaps)
    div_grad_kernel<<<grid, 256>>>(M, mu, out);
}